// round 1
// baseline (speedup 1.0000x reference)
#include <cuda_runtime.h>
#include <stdint.h>

#define N_NODES 50000
#define D       128
#define EH      500000
#define ES      250000
#define NCLS    47

// ---------------- scratch (device globals; no runtime allocation) ----------------
__device__ float g_sumH0[N_NODES * D];
__device__ float g_sumD0[N_NODES * D];
__device__ float g_sumH1[N_NODES * D];
__device__ float g_sumD1[N_NODES * D];
__device__ float g_cntH0[N_NODES];
__device__ float g_cntD0[N_NODES];
__device__ float g_cntH1[N_NODES];
__device__ float g_cntD1[N_NODES];
__device__ float g_H1[N_NODES * D];

// ---------------- zero all accumulators ----------------
__global__ void zero_all_kernel() {
    int i = blockIdx.x * blockDim.x + threadIdx.x;
    const float4 z = make_float4(0.f, 0.f, 0.f, 0.f);
    const int total4 = N_NODES * D / 4;  // 1,600,000
    if (i < total4) {
        ((float4*)g_sumH0)[i] = z;
        ((float4*)g_sumD0)[i] = z;
        ((float4*)g_sumH1)[i] = z;
        ((float4*)g_sumD1)[i] = z;
    }
    if (i < N_NODES / 4) {
        ((float4*)g_cntH0)[i] = z;
        ((float4*)g_cntD0)[i] = z;
        ((float4*)g_cntH1)[i] = z;
        ((float4*)g_cntD1)[i] = z;
    }
}

__device__ __forceinline__ void red_add_v4(float* p, float4 v) {
    asm volatile("red.global.add.v4.f32 [%0], {%1,%2,%3,%4};"
                 :: "l"(p), "f"(v.x), "f"(v.y), "f"(v.z), "f"(v.w)
                 : "memory");
}

// ---------------- scatter-sum: history etype (msg = HBar[src]) ----------------
// One warp per edge; lane l handles float4 chunk l (32*4 = 128 floats).
template <int LAYER>
__global__ void scatter_hist_kernel(const float* __restrict__ hbar,
                                    const int* __restrict__ src,
                                    const int* __restrict__ dst) {
    int gid  = blockIdx.x * blockDim.x + threadIdx.x;
    int e    = gid >> 5;
    int lane = gid & 31;
    if (e >= EH) return;
    float* sum = (LAYER == 0) ? g_sumH0 : g_sumH1;
    float* cnt = (LAYER == 0) ? g_cntH0 : g_cntH1;
    int s = __ldg(src + e);
    int d = __ldg(dst + e);
    float4 v = __ldg((const float4*)(hbar + (size_t)s * D) + lane);
    red_add_v4(sum + (size_t)d * D + lane * 4, v);
    if (lane == 0) atomicAdd(cnt + d, 1.0f);
}

// ---------------- scatter-sum: sampled etype (msg = H[src] - HBar[src]) ----------------
template <int LAYER>
__global__ void scatter_delta_kernel(const float* __restrict__ Hext,
                                     const float* __restrict__ hbar,
                                     const int* __restrict__ src,
                                     const int* __restrict__ dst) {
    int gid  = blockIdx.x * blockDim.x + threadIdx.x;
    int e    = gid >> 5;
    int lane = gid & 31;
    if (e >= ES) return;
    const float* H = (LAYER == 0) ? Hext : g_H1;
    float* sum = (LAYER == 0) ? g_sumD0 : g_sumD1;
    float* cnt = (LAYER == 0) ? g_cntD0 : g_cntD1;
    int s = __ldg(src + e);
    int d = __ldg(dst + e);
    float4 a = __ldg((const float4*)(H    + (size_t)s * D) + lane);
    float4 b = __ldg((const float4*)(hbar + (size_t)s * D) + lane);
    float4 v = make_float4(a.x - b.x, a.y - b.y, a.z - b.z, a.w - b.w);
    red_add_v4(sum + (size_t)d * D + lane * 4, v);
    if (lane == 0) atomicAdd(cnt + d, 1.0f);
}

// ---------------- fused mean + concat + GEMM + bias + ReLU ----------------
// out[r][n] = relu(b[n] + sum_k z[r][k] * W[n][k]),  z = [H_row | neigh_row]
// neigh[j] = sumH[r][j]/max(cntH,1) + sumD[r][j]/max(cntD,1)
// BM=64 rows per block, BK=32, 256 threads, per-thread tile TM=8 x TN=DPAD/32.
template <int LAYER, int DOUT, int DPAD>
__global__ void sage_layer_kernel(const float* __restrict__ Hext,
                                  const float* __restrict__ W,
                                  const float* __restrict__ bias,
                                  float* __restrict__ outext) {
    constexpr int BM = 64, BK = 32, K = 2 * D;
    constexpr int TN = DPAD / 32;
    constexpr int TM = 8;

    const float* H    = (LAYER == 0) ? Hext   : g_H1;
    const float* sumH = (LAYER == 0) ? g_sumH0 : g_sumH1;
    const float* cntH = (LAYER == 0) ? g_cntH0 : g_cntH1;
    const float* sumD = (LAYER == 0) ? g_sumD0 : g_sumD1;
    const float* cntD = (LAYER == 0) ? g_cntD0 : g_cntD1;
    float* out        = (LAYER == 0) ? g_H1   : outext;

    __shared__ float As[BM][BK + 1];
    __shared__ float Bs[BK][DPAD + 1];
    __shared__ float sInvH[BM];
    __shared__ float sInvD[BM];

    int t = threadIdx.x;
    int row0 = blockIdx.x * BM;

    if (t < BM) {
        int r = min(row0 + t, N_NODES - 1);
        sInvH[t] = 1.0f / fmaxf(__ldg(cntH + r), 1.0f);
        sInvD[t] = 1.0f / fmaxf(__ldg(cntD + r), 1.0f);
    }

    int tx = t & 31;       // 32 column groups
    int ty = t >> 5;       // 8 row groups

    float acc[TM][TN];
#pragma unroll
    for (int i = 0; i < TM; i++)
#pragma unroll
        for (int j = 0; j < TN; j++) acc[i][j] = 0.f;

    for (int k0 = 0; k0 < K; k0 += BK) {
        __syncthreads();
        // load A tile (z values): 64x32, 8 elems/thread, coalesced along k
#pragma unroll
        for (int j = 0; j < (BM * BK) / 256; j++) {
            int idx = j * 256 + t;
            int m = idx >> 5, kk = idx & 31;
            int r = min(row0 + m, N_NODES - 1);
            float val;
            if (k0 < D) {
                val = __ldg(H + (size_t)r * D + k0 + kk);
            } else {
                int jj = k0 + kk - D;
                val = __ldg(sumH + (size_t)r * D + jj) * sInvH[m]
                    + __ldg(sumD + (size_t)r * D + jj) * sInvD[m];
            }
            As[m][kk] = val;
        }
        // load B tile (W): BKxDPAD, coalesced along k, conflict-free via +1 pad
#pragma unroll
        for (int j = 0; j < (BK * DPAD) / 256; j++) {
            int idx = j * 256 + t;
            int kk = idx & 31, n = idx >> 5;
            float w = (n < DOUT) ? __ldg(W + n * K + k0 + kk) : 0.f;
            Bs[kk][n] = w;
        }
        __syncthreads();
#pragma unroll
        for (int kk = 0; kk < BK; kk++) {
            float a[TM], bf[TN];
#pragma unroll
            for (int i = 0; i < TM; i++) a[i] = As[ty * TM + i][kk];
#pragma unroll
            for (int j = 0; j < TN; j++) bf[j] = Bs[kk][tx * TN + j];
#pragma unroll
            for (int i = 0; i < TM; i++)
#pragma unroll
                for (int j = 0; j < TN; j++) acc[i][j] += a[i] * bf[j];
        }
    }

    float bn[TN];
#pragma unroll
    for (int j = 0; j < TN; j++) {
        int n = tx * TN + j;
        bn[j] = (n < DOUT) ? __ldg(bias + n) : 0.f;
    }
#pragma unroll
    for (int i = 0; i < TM; i++) {
        int r = row0 + ty * TM + i;
        if (r < N_NODES) {
#pragma unroll
            for (int j = 0; j < TN; j++) {
                int n = tx * TN + j;
                if (n < DOUT)
                    out[(size_t)r * DOUT + n] = fmaxf(acc[i][j] + bn[j], 0.f);
            }
        }
    }
}

// ---------------- launch ----------------
extern "C" void kernel_launch(void* const* d_in, const int* in_sizes, int n_in,
                              void* d_out, int out_size) {
    const float* x     = (const float*)d_in[0];
    const float* hbar0 = (const float*)d_in[1];
    const float* hbar1 = (const float*)d_in[2];
    const float* W0    = (const float*)d_in[3];
    const float* b0    = (const float*)d_in[4];
    const float* W1    = (const float*)d_in[5];
    const float* b1    = (const float*)d_in[6];
    const int* hsrc0   = (const int*)d_in[7];
    const int* hdst0   = (const int*)d_in[8];
    const int* ssrc0   = (const int*)d_in[9];
    const int* sdst0   = (const int*)d_in[10];
    const int* hsrc1   = (const int*)d_in[11];
    const int* hdst1   = (const int*)d_in[12];
    const int* ssrc1   = (const int*)d_in[13];
    const int* sdst1   = (const int*)d_in[14];
    float* out = (float*)d_out;

    // zero accumulators (1.6M threads covers every buffer)
    zero_all_kernel<<<(N_NODES * D / 4 + 255) / 256, 256>>>();

    const int gh = (EH * 32 + 255) / 256;   // warp per edge
    const int gs = (ES * 32 + 255) / 256;
    const int gl = (N_NODES + 63) / 64;     // 782 blocks

    // layer 0
    scatter_hist_kernel<0><<<gh, 256>>>(hbar0, hsrc0, hdst0);
    scatter_delta_kernel<0><<<gs, 256>>>(x, hbar0, ssrc0, sdst0);
    sage_layer_kernel<0, 128, 128><<<gl, 256>>>(x, W0, b0, nullptr);

    // layer 1
    scatter_hist_kernel<1><<<gh, 256>>>(hbar1, hsrc1, hdst1);
    scatter_delta_kernel<1><<<gs, 256>>>(nullptr, hbar1, ssrc1, sdst1);
    sage_layer_kernel<1, NCLS, 64><<<gl, 256>>>(nullptr, W1, b1, out);
}

// round 2
// speedup vs baseline: 1.2990x; 1.2990x over previous
#include <cuda_runtime.h>
#include <stdint.h>

#define N_NODES 50000
#define D       128
#define EH      500000
#define ES      250000
#define NCLS    47

typedef unsigned long long ull;

// ---------------- scratch (device globals; no runtime allocation) ----------------
__device__ float g_sumH0[N_NODES * D];
__device__ float g_sumD0[N_NODES * D];
__device__ float g_sumH1[N_NODES * D];
__device__ float g_sumD1[N_NODES * D];
__device__ float g_cntH0[N_NODES];
__device__ float g_cntD0[N_NODES];
__device__ float g_cntH1[N_NODES];
__device__ float g_cntD1[N_NODES];
__device__ float g_H1[N_NODES * D];

// ---------------- f32x2 packed math helpers ----------------
__device__ __forceinline__ ull fma2(ull a, ull b, ull c) {
    ull d;
    asm("fma.rn.f32x2 %0, %1, %2, %3;" : "=l"(d) : "l"(a), "l"(b), "l"(c));
    return d;
}
__device__ __forceinline__ ull packf2(float x, float y) {
    ull d;
    asm("mov.b64 %0, {%1, %2};" : "=l"(d) : "f"(x), "f"(y));
    return d;
}
__device__ __forceinline__ void unpackf2(ull v, float& x, float& y) {
    asm("mov.b64 {%0, %1}, %2;" : "=f"(x), "=f"(y) : "l"(v));
}

// ---------------- zero all accumulators ----------------
__global__ void zero_all_kernel() {
    int i = blockIdx.x * blockDim.x + threadIdx.x;
    const float4 z = make_float4(0.f, 0.f, 0.f, 0.f);
    const int total4 = N_NODES * D / 4;
    if (i < total4) {
        ((float4*)g_sumH0)[i] = z;
        ((float4*)g_sumD0)[i] = z;
        ((float4*)g_sumH1)[i] = z;
        ((float4*)g_sumD1)[i] = z;
    }
    if (i < N_NODES / 4) {
        ((float4*)g_cntH0)[i] = z;
        ((float4*)g_cntD0)[i] = z;
        ((float4*)g_cntH1)[i] = z;
        ((float4*)g_cntD1)[i] = z;
    }
}

__device__ __forceinline__ void red_add_v4(float* p, float4 v) {
    asm volatile("red.global.add.v4.f32 [%0], {%1,%2,%3,%4};"
                 :: "l"(p), "f"(v.x), "f"(v.y), "f"(v.z), "f"(v.w)
                 : "memory");
}

// ---------------- scatter-sum: history etype (msg = HBar[src]) ----------------
template <int LAYER>
__global__ void scatter_hist_kernel(const float* __restrict__ hbar,
                                    const int* __restrict__ src,
                                    const int* __restrict__ dst) {
    int gid  = blockIdx.x * blockDim.x + threadIdx.x;
    int e    = gid >> 5;
    int lane = gid & 31;
    if (e >= EH) return;
    float* sum = (LAYER == 0) ? g_sumH0 : g_sumH1;
    float* cnt = (LAYER == 0) ? g_cntH0 : g_cntH1;
    int s = __ldg(src + e);
    int d = __ldg(dst + e);
    float4 v = __ldg((const float4*)(hbar + (size_t)s * D) + lane);
    red_add_v4(sum + (size_t)d * D + lane * 4, v);
    if (lane == 0) atomicAdd(cnt + d, 1.0f);
}

// ---------------- scatter-sum: sampled etype (msg = H[src] - HBar[src]) ----------------
template <int LAYER>
__global__ void scatter_delta_kernel(const float* __restrict__ Hext,
                                     const float* __restrict__ hbar,
                                     const int* __restrict__ src,
                                     const int* __restrict__ dst) {
    int gid  = blockIdx.x * blockDim.x + threadIdx.x;
    int e    = gid >> 5;
    int lane = gid & 31;
    if (e >= ES) return;
    const float* H = (LAYER == 0) ? Hext : g_H1;
    float* sum = (LAYER == 0) ? g_sumD0 : g_sumD1;
    float* cnt = (LAYER == 0) ? g_cntD0 : g_cntD1;
    int s = __ldg(src + e);
    int d = __ldg(dst + e);
    float4 a = __ldg((const float4*)(H    + (size_t)s * D) + lane);
    float4 b = __ldg((const float4*)(hbar + (size_t)s * D) + lane);
    float4 v = make_float4(a.x - b.x, a.y - b.y, a.z - b.z, a.w - b.w);
    red_add_v4(sum + (size_t)d * D + lane * 4, v);
    if (lane == 0) atomicAdd(cnt + d, 1.0f);
}

// ---------------- fused mean + concat + GEMM + bias + ReLU ----------------
// out[r][n] = relu(b[n] + sum_k z[r][k] * W[n][k]),  z = [H_row | neigh_row]
// BM=128 x BN tile, BK=32, 256 threads, per-thread TM=8 x TN=BN/16.
// Transposed smem tiles with XOR-swizzled group index (conflict-free STS),
// LDS.128 fragment reads, packed fma.rn.f32x2 compute (pairs along N).
template <int LAYER, int DOUT, int BN>
__global__ void __launch_bounds__(256, 2)
sage_layer_kernel(const float* __restrict__ Hext,
                  const float* __restrict__ W,
                  const float* __restrict__ bias,
                  float* __restrict__ outext) {
    constexpr int BM = 128, BK = 32, K = 2 * D;
    constexpr int TM = 8;
    constexpr int TN = BN / 16;      // 8 (layer0) or 4 (layer1)
    constexpr int TNP = TN / 2;      // packed pairs along N
    constexpr int APAD = BM + 4;     // 132: makes STS swizzle conflict-free
    constexpr int BPAD = BN + 4;

    const float* H    = (LAYER == 0) ? Hext    : g_H1;
    const float* sumH = (LAYER == 0) ? g_sumH0 : g_sumH1;
    const float* cntH = (LAYER == 0) ? g_cntH0 : g_cntH1;
    const float* sumD = (LAYER == 0) ? g_sumD0 : g_sumD1;
    const float* cntD = (LAYER == 0) ? g_cntD0 : g_cntD1;
    float* out        = (LAYER == 0) ? g_H1    : outext;

    __shared__ float As[BK][APAD];
    __shared__ float Bs[BK][BPAD];
    __shared__ float sInvH[BM];
    __shared__ float sInvD[BM];

    const int t    = threadIdx.x;
    const int row0 = blockIdx.x * BM;
    const int tx   = t & 15;   // 16 col groups
    const int ty   = t >> 4;   // 16 row groups

    if (t < BM) {
        int r = min(row0 + t, N_NODES - 1);
        sInvH[t] = 1.0f / fmaxf(__ldg(cntH + r), 1.0f);
        sInvD[t] = 1.0f / fmaxf(__ldg(cntD + r), 1.0f);
    }

    ull acc2[TM][TNP];
#pragma unroll
    for (int i = 0; i < TM; i++)
#pragma unroll
        for (int p = 0; p < TNP; p++) acc2[i][p] = 0ULL;

    for (int kit = 0; kit < K / BK; kit++) {
        const int k0 = kit * BK;
        __syncthreads();

        // ---- load A tile (z values), transposed store with swizzle ----
        // BM*BK/4 = 1024 float4 / 256 thr = 4 per thread
#pragma unroll
        for (int v = 0; v < (BM * BK) / (256 * 4); v++) {
            int id = v * 256 + t;
            int m  = id >> 3;          // 0..127
            int kq = id & 7;           // float4 group along k
            int r  = min(row0 + m, N_NODES - 1);
            float4 val;
            if (k0 < D) {
                val = __ldg((const float4*)(H + (size_t)r * D + k0) + kq);
            } else {
                float4 sh = __ldg((const float4*)(sumH + (size_t)r * D + (k0 - D)) + kq);
                float4 sd = __ldg((const float4*)(sumD + (size_t)r * D + (k0 - D)) + kq);
                float ih = sInvH[m], idl = sInvD[m];
                val = make_float4(sh.x * ih + sd.x * idl, sh.y * ih + sd.y * idl,
                                  sh.z * ih + sd.z * idl, sh.w * ih + sd.w * idl);
            }
            int col = (((m >> 2) ^ (kq >> 1)) << 2) + (m & 3);
            As[(kq << 2) + 0][col] = val.x;
            As[(kq << 2) + 1][col] = val.y;
            As[(kq << 2) + 2][col] = val.z;
            As[(kq << 2) + 3][col] = val.w;
        }

        // ---- load B tile (W), transposed store with swizzle ----
#pragma unroll
        for (int v = 0; v < (BN * BK) / (256 * 4); v++) {
            int id = v * 256 + t;
            int n  = id >> 3;
            int kq = id & 7;
            float4 w = make_float4(0.f, 0.f, 0.f, 0.f);
            if (n < DOUT) w = __ldg((const float4*)(W + n * K + k0) + kq);
            int col = (((n >> 2) ^ (kq >> 1)) << 2) + (n & 3);
            Bs[(kq << 2) + 0][col] = w.x;
            Bs[(kq << 2) + 1][col] = w.y;
            Bs[(kq << 2) + 2][col] = w.z;
            Bs[(kq << 2) + 3][col] = w.w;
        }
        __syncthreads();

        // ---- compute ----
#pragma unroll
        for (int kk = 0; kk < BK; kk++) {
            const int s = (kk >> 3) & 3;
            // a fragment: 8 rows, 2 swizzled float4 groups
            float4 a0 = *(const float4*)&As[kk][(((2 * ty + 0) ^ s) << 2)];
            float4 a1 = *(const float4*)&As[kk][(((2 * ty + 1) ^ s) << 2)];
            ull ad[TM];
            ad[0] = packf2(a0.x, a0.x); ad[1] = packf2(a0.y, a0.y);
            ad[2] = packf2(a0.z, a0.z); ad[3] = packf2(a0.w, a0.w);
            ad[4] = packf2(a1.x, a1.x); ad[5] = packf2(a1.y, a1.y);
            ad[6] = packf2(a1.z, a1.z); ad[7] = packf2(a1.w, a1.w);
            // b fragment: TN cols = TN/4 swizzled float4 groups, packed in pairs
            ull bp[TNP];
#pragma unroll
            for (int u = 0; u < TN / 4; u++) {
                int g = (tx * (TN / 4) + u) ^ s;   // group idx within BN/4
                float4 b = *(const float4*)&Bs[kk][g << 2];
                bp[2 * u + 0] = packf2(b.x, b.y);
                bp[2 * u + 1] = packf2(b.z, b.w);
            }
#pragma unroll
            for (int i = 0; i < TM; i++)
#pragma unroll
                for (int p = 0; p < TNP; p++)
                    acc2[i][p] = fma2(ad[i], bp[p], acc2[i][p]);
        }
    }

    // ---- epilogue: bias + relu + store ----
    float bn[TN];
#pragma unroll
    for (int j = 0; j < TN; j++) {
        int n = tx * TN + j;
        bn[j] = (n < DOUT) ? __ldg(bias + n) : 0.f;
    }
#pragma unroll
    for (int i = 0; i < TM; i++) {
        int r = row0 + ty * TM + i;
        if (r >= N_NODES) continue;
        float res[TN];
#pragma unroll
        for (int p = 0; p < TNP; p++) {
            float lo, hi;
            unpackf2(acc2[i][p], lo, hi);
            res[2 * p + 0] = fmaxf(lo + bn[2 * p + 0], 0.f);
            res[2 * p + 1] = fmaxf(hi + bn[2 * p + 1], 0.f);
        }
        if (DOUT == BN) {
            // dense store (layer0): float4s
#pragma unroll
            for (int u = 0; u < TN / 4; u++) {
                float4 o = make_float4(res[4 * u], res[4 * u + 1], res[4 * u + 2], res[4 * u + 3]);
                *(float4*)(out + (size_t)r * DOUT + tx * TN + 4 * u) = o;
            }
        } else {
#pragma unroll
            for (int j = 0; j < TN; j++) {
                int n = tx * TN + j;
                if (n < DOUT) out[(size_t)r * DOUT + n] = res[j];
            }
        }
    }
}

// ---------------- launch ----------------
extern "C" void kernel_launch(void* const* d_in, const int* in_sizes, int n_in,
                              void* d_out, int out_size) {
    const float* x     = (const float*)d_in[0];
    const float* hbar0 = (const float*)d_in[1];
    const float* hbar1 = (const float*)d_in[2];
    const float* W0    = (const float*)d_in[3];
    const float* b0    = (const float*)d_in[4];
    const float* W1    = (const float*)d_in[5];
    const float* b1    = (const float*)d_in[6];
    const int* hsrc0   = (const int*)d_in[7];
    const int* hdst0   = (const int*)d_in[8];
    const int* ssrc0   = (const int*)d_in[9];
    const int* sdst0   = (const int*)d_in[10];
    const int* hsrc1   = (const int*)d_in[11];
    const int* hdst1   = (const int*)d_in[12];
    const int* ssrc1   = (const int*)d_in[13];
    const int* sdst1   = (const int*)d_in[14];
    float* out = (float*)d_out;

    zero_all_kernel<<<(N_NODES * D / 4 + 255) / 256, 256>>>();

    const int gh = (EH * 32 + 255) / 256;
    const int gs = (ES * 32 + 255) / 256;
    const int gl = (N_NODES + 127) / 128;   // 391 blocks

    // layer 0
    scatter_hist_kernel<0><<<gh, 256>>>(hbar0, hsrc0, hdst0);
    scatter_delta_kernel<0><<<gs, 256>>>(x, hbar0, ssrc0, sdst0);
    sage_layer_kernel<0, 128, 128><<<gl, 256>>>(x, W0, b0, nullptr);

    // layer 1
    scatter_hist_kernel<1><<<gh, 256>>>(hbar1, hsrc1, hdst1);
    scatter_delta_kernel<1><<<gs, 256>>>(nullptr, hbar1, ssrc1, sdst1);
    sage_layer_kernel<1, NCLS, 64><<<gl, 256>>>(nullptr, W1, b1, out);
}